// round 15
// baseline (speedup 1.0000x reference)
#include <cuda_runtime.h>

// ---------------- problem constants ----------------
#define N_PTS 32768
#define TILE 2048
#define T_TILES (N_PTS / TILE)                        // 16
#define NPAIR_BLOCKS (T_TILES * (T_TILES + 1) / 2)    // 136 pair blocks
#define NEDGE_BLOCKS 12
#define NTOTAL_BLOCKS (NPAIR_BLOCKS + NEDGE_BLOCKS)   // 148 = 1 block per SM
#define THREADS 1024
#define JH (TILE / 2)                                 // 1024 j per thread-half
#define ILANES 512                                    // i-lanes per half
#define IB (TILE / ILANES)                            // 4 i-points per thread
#define NG (IB / 2)                                   // 2 packed i-groups
#define SCALE 3.5f
#define SCALE2 12.25f

// ---------------- device scratch (no allocs allowed) ----------------
__device__ double g_part[NPAIR_BLOCKS];   // per-pair-block sums
__device__ double g_e1[NEDGE_BLOCKS];     // sum p*log(1+d2)
__device__ double g_e2[NEDGE_BLOCKS];     // sum p
__device__ double g_e3[NEDGE_BLOCKS];     // sum p*log(p)
__device__ int    g_done;                 // completion counter (self-resetting)

typedef unsigned long long u64;

__device__ __forceinline__ float frcp(float x) {
    float r;
    asm("rcp.approx.ftz.f32 %0, %1;" : "=f"(r) : "f"(x));
    return r;
}
__device__ __forceinline__ u64 pack2(float lo, float hi) {
    u64 r;
    asm("mov.b64 %0, {%1, %2};" : "=l"(r) : "f"(lo), "f"(hi));
    return r;
}
__device__ __forceinline__ void unpack2(u64 v, float& lo, float& hi) {
    asm("mov.b64 {%0, %1}, %2;" : "=f"(lo), "=f"(hi) : "l"(v));
}
__device__ __forceinline__ u64 fma2(u64 a, u64 b, u64 c) {
    u64 d;
    asm("fma.rn.f32x2 %0, %1, %2, %3;" : "=l"(d) : "l"(a), "l"(b), "l"(c));
    return d;
}
__device__ __forceinline__ u64 add2(u64 a, u64 b) {
    u64 d;
    asm("add.rn.f32x2 %0, %1, %2;" : "=l"(d) : "l"(a), "l"(b));
    return d;
}
__device__ __forceinline__ u64 mul2(u64 a, u64 b) {
    u64 d;
    asm("mul.rn.f32x2 %0, %1, %2;" : "=l"(d) : "l"(a), "l"(b));
    return d;
}

// ---------------- single fused kernel ----------------------------------------
// 148 blocks x 1024 threads = 1 block/SM, single wave.
// Blocks [0,136): PURE pair work -- one full 2048x2048 tile-square each
//   (j-split across thread halves; diagonal squares once, off-diagonal doubled).
// Blocks [136,148): ALL positive-edge terms, 4-batched gathers (MLP>=4),
//   ~25-30us, fully hidden under the ~125us pair window.
// Last block to finish assembles the scalar.
__global__ void __launch_bounds__(THREADS, 1) k_fused(
        const float2* __restrict__ emb,
        const float* __restrict__ p,
        const int* __restrict__ heads,
        const int* __restrict__ tails,
        int E, int n, float* __restrict__ out) {
    __shared__ __align__(16) u64 sx[TILE];
    __shared__ __align__(16) u64 sy[TILE];
    __shared__ __align__(16) u64 sz[TILE];

    int q = blockIdx.x;

    if (q < NPAIR_BLOCKS) {
        // ================= pure pair block =================
        int t = q;
        int r = (int)((sqrtf(8.0f * (float)t + 1.0f) - 1.0f) * 0.5f);
        while ((r + 1) * (r + 2) / 2 <= t) r++;
        while (r * (r + 1) / 2 > t) r--;
        int c = t - r * (r + 1) / 2;
        int bi = c, bj = r;  // bi <= bj

        int jbase = bj * TILE;
        int ibase = bi * TILE;

        for (int k = threadIdx.x; k < TILE; k += THREADS) {
            float2 e = emb[jbase + k];
            float x = e.x * SCALE;
            float y = e.y * SCALE;
            float sq = fmaf(x, x, y * y);
            sx[k] = pack2(x, x);
            sy[k] = pack2(y, y);
            sz[k] = pack2(1.0f + sq, 1.0f + sq);
        }
        __syncthreads();

        // j-split: warps 0-15 -> j in [0,JH), warps 16-31 -> [JH,TILE)
        int jstart = (threadIdx.x >> 9) * JH;
        int ilane = threadIdx.x & (ILANES - 1);

        u64 m2[NG], n2[NG], s2[NG], acc2[NG];
        int i0 = ibase + ilane * IB;
#pragma unroll
        for (int g = 0; g < NG; g++) {
            float2 ea = emb[i0 + 2 * g];
            float2 eb = emb[i0 + 2 * g + 1];
            float xa = ea.x * SCALE, ya = ea.y * SCALE;
            float xb = eb.x * SCALE, yb = eb.y * SCALE;
            m2[g] = pack2(-2.0f * xa, -2.0f * xb);
            n2[g] = pack2(-2.0f * ya, -2.0f * yb);
            s2[g] = pack2(fmaf(xa, xa, ya * ya), fmaf(xb, xb, yb * yb));
            acc2[g] = pack2(0.0f, 0.0f);
        }

#pragma unroll 4
        for (int j = jstart; j < jstart + JH; j += 2) {
            ulonglong2 JX = *reinterpret_cast<const ulonglong2*>(&sx[j]);
            ulonglong2 JY = *reinterpret_cast<const ulonglong2*>(&sy[j]);
            ulonglong2 JZ = *reinterpret_cast<const ulonglong2*>(&sz[j]);
#pragma unroll
            for (int g = 0; g < NG; g++) {
                u64 d1 = fma2(m2[g], JX.x, fma2(n2[g], JY.x, add2(JZ.x, s2[g])));
                u64 d2 = fma2(m2[g], JX.y, fma2(n2[g], JY.y, add2(JZ.y, s2[g])));
                u64 pr = mul2(d1, d2);
                u64 sm = add2(d1, d2);
                float plo, phi;
                unpack2(pr, plo, phi);
                u64 r2 = pack2(frcp(plo), frcp(phi));
                acc2[g] = fma2(sm, r2, acc2[g]);
            }
        }

        double dsum = 0.0;
#pragma unroll
        for (int g = 0; g < NG; g++) {
            float lo, hi;
            unpack2(acc2[g], lo, hi);
            dsum += (double)lo + (double)hi;
        }
        if (bi != bj) dsum *= 2.0;  // symmetry doubling

#pragma unroll
        for (int o = 16; o > 0; o >>= 1)
            dsum += __shfl_down_sync(0xffffffffu, dsum, o);

        double* sred = reinterpret_cast<double*>(sx);
        __syncthreads();
        if ((threadIdx.x & 31) == 0)
            sred[threadIdx.x >> 5] = dsum;
        __syncthreads();
        if (threadIdx.x == 0) {
            double v = 0.0;
#pragma unroll
            for (int w = 0; w < THREADS / 32; w++) v += sred[w];
            g_part[q] = v;
        }
    } else {
        // ================= dedicated edge block: all of [0, E) ============
        int b = q - NPAIR_BLOCKS;
        int lane = b * THREADS + threadIdx.x;
        int nlanes = NEDGE_BLOCKS * THREADS;
        float s1 = 0.0f, sp = 0.0f, se = 0.0f;

        int stride = nlanes * 4;
        int i = lane * 4;
        for (; i + 4 <= E; i += stride) {
            int h0 = heads[i],     h1 = heads[i + 1], h2 = heads[i + 2], h3 = heads[i + 3];
            int t0 = tails[i],     t1 = tails[i + 1], t2 = tails[i + 2], t3 = tails[i + 3];
            float2 A0 = emb[h0], A1 = emb[h1], A2 = emb[h2], A3 = emb[h3];
            float2 B0 = emb[t0], B1 = emb[t1], B2 = emb[t2], B3 = emb[t3];
            float p0 = p[i], p1 = p[i + 1], p2 = p[i + 2], p3 = p[i + 3];
            float dx, dy, d2;
            dx = A0.x - B0.x; dy = A0.y - B0.y; d2 = SCALE2 * fmaf(dx, dx, dy * dy);
            s1 = fmaf(p0, __logf(1.0f + d2), s1); sp += p0; se = fmaf(p0, __logf(p0), se);
            dx = A1.x - B1.x; dy = A1.y - B1.y; d2 = SCALE2 * fmaf(dx, dx, dy * dy);
            s1 = fmaf(p1, __logf(1.0f + d2), s1); sp += p1; se = fmaf(p1, __logf(p1), se);
            dx = A2.x - B2.x; dy = A2.y - B2.y; d2 = SCALE2 * fmaf(dx, dx, dy * dy);
            s1 = fmaf(p2, __logf(1.0f + d2), s1); sp += p2; se = fmaf(p2, __logf(p2), se);
            dx = A3.x - B3.x; dy = A3.y - B3.y; d2 = SCALE2 * fmaf(dx, dx, dy * dy);
            s1 = fmaf(p3, __logf(1.0f + d2), s1); sp += p3; se = fmaf(p3, __logf(p3), se);
        }
        for (int k = i; k < E; k++) {  // stragglers (E%4 != 0 case)
            int h = heads[k], tl = tails[k];
            float2 A = emb[h], B = emb[tl];
            float dx = A.x - B.x, dy = A.y - B.y;
            float d2 = SCALE2 * fmaf(dx, dx, dy * dy);
            float pe = p[k];
            s1 = fmaf(pe, __logf(1.0f + d2), s1); sp += pe;
            se = fmaf(pe, __logf(pe), se);
        }

        double d1 = (double)s1, d2s = (double)sp, d3 = (double)se;
#pragma unroll
        for (int o = 16; o > 0; o >>= 1) {
            d1  += __shfl_down_sync(0xffffffffu, d1, o);
            d2s += __shfl_down_sync(0xffffffffu, d2s, o);
            d3  += __shfl_down_sync(0xffffffffu, d3, o);
        }
        double* sh1 = reinterpret_cast<double*>(sy);
        double* sh2 = sh1 + (THREADS / 32);
        double* sh3 = sh2 + (THREADS / 32);
        __syncthreads();
        if ((threadIdx.x & 31) == 0) {
            int w = threadIdx.x >> 5;
            sh1[w] = d1; sh2[w] = d2s; sh3[w] = d3;
        }
        __syncthreads();
        if (threadIdx.x == 0) {
            double v1 = 0.0, v2 = 0.0, v3 = 0.0;
#pragma unroll
            for (int w = 0; w < THREADS / 32; w++) {
                v1 += sh1[w]; v2 += sh2[w]; v3 += sh3[w];
            }
            g_e1[b] = v1; g_e2[b] = v2; g_e3[b] = v3;
        }
    }

    // ================= last block assembles the scalar =================
    int lastflag = 0;
    if (threadIdx.x == 0) {
        __threadfence();  // make this block's partials visible
        lastflag = (atomicAdd(&g_done, 1) == NTOTAL_BLOCKS - 1) ? 1 : 0;
    }
    if (threadIdx.x < 32) {
        lastflag = __shfl_sync(0xffffffffu, lastflag, 0);
        if (lastflag) {
            __threadfence();  // acquire all other blocks' partials
            double z = 0.0, e1 = 0.0, e2 = 0.0, e3 = 0.0;
            for (int i = threadIdx.x; i < NPAIR_BLOCKS; i += 32) z += g_part[i];
            if (threadIdx.x < NEDGE_BLOCKS) {
                e1 = g_e1[threadIdx.x];
                e2 = g_e2[threadIdx.x];
                e3 = g_e3[threadIdx.x];
            }
#pragma unroll
            for (int o = 16; o > 0; o >>= 1) {
                z  += __shfl_down_sync(0xffffffffu, z, o);
                e1 += __shfl_down_sync(0xffffffffu, e1, o);
                e2 += __shfl_down_sync(0xffffffffu, e2, o);
                e3 += __shfl_down_sync(0xffffffffu, e3, o);
            }
            if (threadIdx.x == 0) {
                double Z = z - (double)n;  // remove diagonal (each term = 1)
                out[0] = (float)(e1 + log(Z) * e2 + e3);
                g_done = 0;  // self-reset for graph replay determinism
            }
        }
    }
}

// ---------------- launch ------------------------------------------------------
extern "C" void kernel_launch(void* const* d_in, const int* in_sizes, int n_in,
                              void* d_out, int out_size) {
    const float2* emb   = (const float2*)d_in[0];
    const float*  p     = (const float*)d_in[1];
    const int*    heads = (const int*)d_in[2];
    const int*    tails = (const int*)d_in[3];
    int n = in_sizes[0] / 2;
    int E = in_sizes[1];

    k_fused<<<NTOTAL_BLOCKS, THREADS>>>(emb, p, heads, tails, E, n, (float*)d_out);
}

// round 16
// speedup vs baseline: 1.3323x; 1.3323x over previous
#include <cuda_runtime.h>

// ---------------- problem constants ----------------
#define N_PTS 32768
#define TILE 2048
#define T_TILES (N_PTS / TILE)                        // 16
#define NPAIR_BLOCKS (T_TILES * (T_TILES + 1) / 2)    // 136 pair blocks
#define NEDGE_BLOCKS 12
#define NTOTAL_BLOCKS (NPAIR_BLOCKS + NEDGE_BLOCKS)   // 148 = 1 block per SM
#define THREADS 1024
#define JH (TILE / 2)                                 // 1024 j per thread-half
#define ILANES 512                                    // i-lanes per half
#define IB (TILE / ILANES)                            // 4 i-points per thread
#define NG (IB / 2)                                   // 2 packed i-groups
#define SCALE 3.5f
#define SCALE2 12.25f

// ---------------- device scratch (no allocs allowed) ----------------
__device__ double g_part[NPAIR_BLOCKS];   // per-pair-block sums
__device__ double g_e1[NTOTAL_BLOCKS];    // per-block sum p*log(1+d2)
__device__ double g_e2[NTOTAL_BLOCKS];    // per-block sum p
__device__ double g_e3[NTOTAL_BLOCKS];    // per-block sum p*log(p)
__device__ int    g_done;                 // completion counter (self-resetting)

typedef unsigned long long u64;

__device__ __forceinline__ float frcp(float x) {
    float r;
    asm("rcp.approx.ftz.f32 %0, %1;" : "=f"(r) : "f"(x));
    return r;
}
__device__ __forceinline__ u64 pack2(float lo, float hi) {
    u64 r;
    asm("mov.b64 %0, {%1, %2};" : "=l"(r) : "f"(lo), "f"(hi));
    return r;
}
__device__ __forceinline__ void unpack2(u64 v, float& lo, float& hi) {
    asm("mov.b64 {%0, %1}, %2;" : "=f"(lo), "=f"(hi) : "l"(v));
}
__device__ __forceinline__ u64 fma2(u64 a, u64 b, u64 c) {
    u64 d;
    asm("fma.rn.f32x2 %0, %1, %2, %3;" : "=l"(d) : "l"(a), "l"(b), "l"(c));
    return d;
}
__device__ __forceinline__ u64 add2(u64 a, u64 b) {
    u64 d;
    asm("add.rn.f32x2 %0, %1, %2;" : "=l"(d) : "l"(a), "l"(b));
    return d;
}

// -------- batched edge accumulator: 4 edges in flight (MLP>=4) --------
__device__ __forceinline__ void edge_range(
        const float2* __restrict__ emb, const float* __restrict__ p,
        const int* __restrict__ heads, const int* __restrict__ tails,
        int start, int end, int lane, int nlanes,
        float& s1, float& sp, float& se) {
    int stride = nlanes * 4;
    int i = start + lane * 4;
    for (; i + 4 <= end; i += stride) {
        int h0 = heads[i],     h1 = heads[i + 1], h2 = heads[i + 2], h3 = heads[i + 3];
        int t0 = tails[i],     t1 = tails[i + 1], t2 = tails[i + 2], t3 = tails[i + 3];
        float2 A0 = emb[h0], A1 = emb[h1], A2 = emb[h2], A3 = emb[h3];
        float2 B0 = emb[t0], B1 = emb[t1], B2 = emb[t2], B3 = emb[t3];
        float p0 = p[i], p1 = p[i + 1], p2 = p[i + 2], p3 = p[i + 3];
        float dx, dy, d2;
        dx = A0.x - B0.x; dy = A0.y - B0.y; d2 = SCALE2 * fmaf(dx, dx, dy * dy);
        s1 = fmaf(p0, __logf(1.0f + d2), s1); sp += p0; se = fmaf(p0, __logf(p0), se);
        dx = A1.x - B1.x; dy = A1.y - B1.y; d2 = SCALE2 * fmaf(dx, dx, dy * dy);
        s1 = fmaf(p1, __logf(1.0f + d2), s1); sp += p1; se = fmaf(p1, __logf(p1), se);
        dx = A2.x - B2.x; dy = A2.y - B2.y; d2 = SCALE2 * fmaf(dx, dx, dy * dy);
        s1 = fmaf(p2, __logf(1.0f + d2), s1); sp += p2; se = fmaf(p2, __logf(p2), se);
        dx = A3.x - B3.x; dy = A3.y - B3.y; d2 = SCALE2 * fmaf(dx, dx, dy * dy);
        s1 = fmaf(p3, __logf(1.0f + d2), s1); sp += p3; se = fmaf(p3, __logf(p3), se);
    }
    for (int k = i; k < end && k >= i; k++) {
        if (k >= end) break;
    }
    if (i < end) {
        for (int k = i; k < end; k++) {
            int h = heads[k], tl = tails[k];
            float2 A = emb[h], B = emb[tl];
            float dx = A.x - B.x, dy = A.y - B.y;
            float d2 = SCALE2 * fmaf(dx, dx, dy * dy);
            float pe = p[k];
            s1 = fmaf(pe, __logf(1.0f + d2), s1); sp += pe;
            se = fmaf(pe, __logf(pe), se);
        }
    }
}

// ---------------- single fused kernel ----------------------------------------
// 148 blocks x 1024 threads = 1 block/SM.
// Blocks [0,136): one full 2048x2048 tile-square of pair terms each (j-split
//   across thread halves) + a striped slice of edges [E2, E).
// Blocks [136,148): edges [0, E2) only (hidden under the pair window).
// Inner loop: DIRECT per-pair reciprocals (no combining) -- shifts work from
// the saturated fma pipe (9 -> 8 cyc/pair) onto the half-idle MUFU pipe,
// balancing both at ~227K cyc/SMSP.
__global__ void __launch_bounds__(THREADS, 1) k_fused(
        const float2* __restrict__ emb,
        const float* __restrict__ p,
        const int* __restrict__ heads,
        const int* __restrict__ tails,
        int E, int n, float* __restrict__ out) {
    __shared__ __align__(16) u64 sx[TILE];
    __shared__ __align__(16) u64 sy[TILE];
    __shared__ __align__(16) u64 sz[TILE];

    int q = blockIdx.x;
    int E2 = (E / 2) & ~3;  // split point, multiple of 4

    float s1 = 0.0f, sp = 0.0f, se = 0.0f;

    if (q < NPAIR_BLOCKS) {
        // ================= pair tile =================
        int t = q;
        int r = (int)((sqrtf(8.0f * (float)t + 1.0f) - 1.0f) * 0.5f);
        while ((r + 1) * (r + 2) / 2 <= t) r++;
        while (r * (r + 1) / 2 > t) r--;
        int c = t - r * (r + 1) / 2;
        int bi = c, bj = r;  // bi <= bj

        int jbase = bj * TILE;
        int ibase = bi * TILE;

        for (int k = threadIdx.x; k < TILE; k += THREADS) {
            float2 e = emb[jbase + k];
            float x = e.x * SCALE;
            float y = e.y * SCALE;
            float sq = fmaf(x, x, y * y);
            sx[k] = pack2(x, x);
            sy[k] = pack2(y, y);
            sz[k] = pack2(1.0f + sq, 1.0f + sq);
        }
        __syncthreads();

        // j-split: warps 0-15 -> j in [0,JH), warps 16-31 -> [JH,TILE)
        int jstart = (threadIdx.x >> 9) * JH;
        int ilane = threadIdx.x & (ILANES - 1);

        u64 m2[NG], n2[NG], s2[NG];
        float acc[NG * 4];
        int i0 = ibase + ilane * IB;
#pragma unroll
        for (int g = 0; g < NG; g++) {
            float2 ea = emb[i0 + 2 * g];
            float2 eb = emb[i0 + 2 * g + 1];
            float xa = ea.x * SCALE, ya = ea.y * SCALE;
            float xb = eb.x * SCALE, yb = eb.y * SCALE;
            m2[g] = pack2(-2.0f * xa, -2.0f * xb);
            n2[g] = pack2(-2.0f * ya, -2.0f * yb);
            s2[g] = pack2(fmaf(xa, xa, ya * ya), fmaf(xb, xb, yb * yb));
            acc[4 * g + 0] = 0.0f; acc[4 * g + 1] = 0.0f;
            acc[4 * g + 2] = 0.0f; acc[4 * g + 3] = 0.0f;
        }

#pragma unroll 2
        for (int j = jstart; j < jstart + JH; j += 2) {
            ulonglong2 JX = *reinterpret_cast<const ulonglong2*>(&sx[j]);
            ulonglong2 JY = *reinterpret_cast<const ulonglong2*>(&sy[j]);
            ulonglong2 JZ = *reinterpret_cast<const ulonglong2*>(&sz[j]);
#pragma unroll
            for (int g = 0; g < NG; g++) {
                // packed denominators for (i_2g, i_2g+1) x j and x (j+1)
                u64 d1 = fma2(m2[g], JX.x, fma2(n2[g], JY.x, add2(JZ.x, s2[g])));
                u64 d2 = fma2(m2[g], JX.y, fma2(n2[g], JY.y, add2(JZ.y, s2[g])));
                float a0, a1, b0, b1;
                unpack2(d1, a0, a1);
                unpack2(d2, b0, b1);
                // direct reciprocal per pair (MUFU), independent scalar accs
                acc[4 * g + 0] += frcp(a0);
                acc[4 * g + 1] += frcp(a1);
                acc[4 * g + 2] += frcp(b0);
                acc[4 * g + 3] += frcp(b1);
            }
        }

        double dsum = 0.0;
#pragma unroll
        for (int k = 0; k < NG * 4; k++) dsum += (double)acc[k];
        if (bi != bj) dsum *= 2.0;  // symmetry doubling

#pragma unroll
        for (int o = 16; o > 0; o >>= 1)
            dsum += __shfl_down_sync(0xffffffffu, dsum, o);

        double* sred = reinterpret_cast<double*>(sx);
        __syncthreads();
        if ((threadIdx.x & 31) == 0)
            sred[threadIdx.x >> 5] = dsum;
        __syncthreads();
        if (threadIdx.x == 0) {
            double v = 0.0;
#pragma unroll
            for (int w = 0; w < THREADS / 32; w++) v += sred[w];
            g_part[q] = v;
        }

        // ---- striped edge slice: [E2, E) over 136 blocks, batched ----
        edge_range(emb, p, heads, tails, E2, E,
                   q * THREADS + threadIdx.x, NPAIR_BLOCKS * THREADS,
                   s1, sp, se);
    } else {
        // ================= dedicated edge block: [0, E2) =================
        int b = q - NPAIR_BLOCKS;
        edge_range(emb, p, heads, tails, 0, E2,
                   b * THREADS + threadIdx.x, NEDGE_BLOCKS * THREADS,
                   s1, sp, se);
    }

    // block reduction of edge partials
    {
        double d1 = (double)s1, d2s = (double)sp, d3 = (double)se;
#pragma unroll
        for (int o = 16; o > 0; o >>= 1) {
            d1  += __shfl_down_sync(0xffffffffu, d1, o);
            d2s += __shfl_down_sync(0xffffffffu, d2s, o);
            d3  += __shfl_down_sync(0xffffffffu, d3, o);
        }
        double* sh1 = reinterpret_cast<double*>(sy);
        double* sh2 = sh1 + (THREADS / 32);
        double* sh3 = sh2 + (THREADS / 32);
        __syncthreads();
        if ((threadIdx.x & 31) == 0) {
            int w = threadIdx.x >> 5;
            sh1[w] = d1; sh2[w] = d2s; sh3[w] = d3;
        }
        __syncthreads();
        if (threadIdx.x == 0) {
            double v1 = 0.0, v2 = 0.0, v3 = 0.0;
#pragma unroll
            for (int w = 0; w < THREADS / 32; w++) {
                v1 += sh1[w]; v2 += sh2[w]; v3 += sh3[w];
            }
            g_e1[q] = v1; g_e2[q] = v2; g_e3[q] = v3;
        }
    }

    // ================= last block assembles the scalar =================
    int lastflag = 0;
    if (threadIdx.x == 0) {
        __threadfence();  // make this block's partials visible
        lastflag = (atomicAdd(&g_done, 1) == NTOTAL_BLOCKS - 1) ? 1 : 0;
    }
    if (threadIdx.x < 32) {
        lastflag = __shfl_sync(0xffffffffu, lastflag, 0);
        if (lastflag) {
            __threadfence();  // acquire all other blocks' partials
            double z = 0.0, e1 = 0.0, e2 = 0.0, e3 = 0.0;
            for (int i = threadIdx.x; i < NTOTAL_BLOCKS; i += 32) {
                if (i < NPAIR_BLOCKS) z += g_part[i];
                e1 += g_e1[i];
                e2 += g_e2[i];
                e3 += g_e3[i];
            }
#pragma unroll
            for (int o = 16; o > 0; o >>= 1) {
                z  += __shfl_down_sync(0xffffffffu, z, o);
                e1 += __shfl_down_sync(0xffffffffu, e1, o);
                e2 += __shfl_down_sync(0xffffffffu, e2, o);
                e3 += __shfl_down_sync(0xffffffffu, e3, o);
            }
            if (threadIdx.x == 0) {
                double Z = z - (double)n;  // remove diagonal (each term = 1)
                out[0] = (float)(e1 + log(Z) * e2 + e3);
                g_done = 0;  // self-reset for graph replay determinism
            }
        }
    }
}

// ---------------- launch ------------------------------------------------------
extern "C" void kernel_launch(void* const* d_in, const int* in_sizes, int n_in,
                              void* d_out, int out_size) {
    const float2* emb   = (const float2*)d_in[0];
    const float*  p     = (const float*)d_in[1];
    const int*    heads = (const int*)d_in[2];
    const int*    tails = (const int*)d_in[3];
    int n = in_sizes[0] / 2;
    int E = in_sizes[1];

    k_fused<<<NTOTAL_BLOCKS, THREADS>>>(emb, p, heads, tails, E, n, (float*)d_out);
}

// round 17
// speedup vs baseline: 1.7642x; 1.3242x over previous
#include <cuda_runtime.h>

// ---------------- problem constants ----------------
#define N_PTS 32768
#define TILE_I 4096                                   // i-extent per block
#define TILE_J 1024                                   // j-extent per block
#define T_TILES (N_PTS / TILE_I)                      // 8
#define NSQUARES (T_TILES * (T_TILES + 1) / 2)        // 36 tile-squares
#define JCHUNKS (TILE_I / TILE_J)                     // 4
#define NPAIR_BLOCKS (NSQUARES * JCHUNKS)             // 144 blocks, 1 per SM
#define THREADS 1024
#define IB 4                                          // i-points per thread (1024*4 = 4096)
#define SCALE 3.5f
#define SCALE2 12.25f

// ---------------- device scratch (no allocs allowed) ----------------
__device__ double g_part[NPAIR_BLOCKS];  // per-block pair sums
__device__ double g_e1[NPAIR_BLOCKS];    // per-block sum p*log(1+d2)
__device__ double g_e2[NPAIR_BLOCKS];    // per-block sum p
__device__ double g_e3[NPAIR_BLOCKS];    // per-block sum p*log(p)
__device__ int    g_done;                // completion counter (self-resetting)

typedef unsigned long long u64;

__device__ __forceinline__ float frcp(float x) {
    float r;
    asm("rcp.approx.ftz.f32 %0, %1;" : "=f"(r) : "f"(x));
    return r;
}
__device__ __forceinline__ u64 pack2(float lo, float hi) {
    u64 r;
    asm("mov.b64 %0, {%1, %2};" : "=l"(r) : "f"(lo), "f"(hi));
    return r;
}
__device__ __forceinline__ void unpack2(u64 v, float& lo, float& hi) {
    asm("mov.b64 {%0, %1}, %2;" : "=f"(lo), "=f"(hi) : "l"(v));
}
__device__ __forceinline__ u64 fma2(u64 a, u64 b, u64 c) {
    u64 d;
    asm("fma.rn.f32x2 %0, %1, %2, %3;" : "=l"(d) : "l"(a), "l"(b), "l"(c));
    return d;
}
__device__ __forceinline__ u64 add2(u64 a, u64 b) {
    u64 d;
    asm("add.rn.f32x2 %0, %1, %2;" : "=l"(d) : "l"(a), "l"(b));
    return d;
}
__device__ __forceinline__ u64 mul2(u64 a, u64 b) {
    u64 d;
    asm("mul.rn.f32x2 %0, %1, %2;" : "=l"(d) : "l"(a), "l"(b));
    return d;
}

// ---------------- single fused kernel ----------------------------------------
// R11 frame (144 blocks x 1024 threads, 4096x1024 rectangles), NEW inner loop:
// j-PAIR packing. smem holds (xj0,xj1),(yj0,yj1),(zj0,zj1) packed by j-pair;
// i-values are duplicated (mi,mi) in registers. One fma2 => (i x j0, i x j1).
// Per i per j-quad: 9 fma-pipe inst + 2 MUFU for 4 pairs (same as R11) but the
// 3 LDS.128 per j-quad are SHARED across all IB=4 i's (R11 needed 6).
__global__ void __launch_bounds__(THREADS, 1) k_fused(
        const float2* __restrict__ emb,
        const float* __restrict__ p,
        const int* __restrict__ heads,
        const int* __restrict__ tails,
        int E, int n, float* __restrict__ out) {
    __shared__ __align__(16) u64 sxp[TILE_J / 2];  // (x_{2k}, x_{2k+1})
    __shared__ __align__(16) u64 syp[TILE_J / 2];  // (y_{2k}, y_{2k+1})
    __shared__ __align__(16) u64 szp[TILE_J / 2];  // (z_{2k}, z_{2k+1}), z=1+sq

    int q = blockIdx.x;

    // ================= phase 1: pair rectangle =================
    {
        int t = q >> 2;          // square id (0..35)
        int chunk = q & 3;       // j-chunk within the square
        int r = (int)((sqrtf(8.0f * (float)t + 1.0f) - 1.0f) * 0.5f);
        while ((r + 1) * (r + 2) / 2 <= t) r++;
        while (r * (r + 1) / 2 > t) r--;
        int c = t - r * (r + 1) / 2;
        int bi = c, bj = r;  // bi <= bj

        int jbase = bj * TILE_I + chunk * TILE_J;
        int ibase = bi * TILE_I;

        // cooperative j-tile load: pack j-PAIRS
        for (int k = threadIdx.x; k < TILE_J / 2; k += THREADS) {
            float2 e0 = emb[jbase + 2 * k];
            float2 e1 = emb[jbase + 2 * k + 1];
            float x0 = e0.x * SCALE, y0 = e0.y * SCALE;
            float x1 = e1.x * SCALE, y1 = e1.y * SCALE;
            sxp[k] = pack2(x0, x1);
            syp[k] = pack2(y0, y1);
            szp[k] = pack2(fmaf(x0, x0, fmaf(y0, y0, 1.0f)),
                           fmaf(x1, x1, fmaf(y1, y1, 1.0f)));
        }
        __syncthreads();

        // per-thread i-points: IB=4 consecutive; i-values DUPLICATED (v,v)
        u64 M[IB], N_[IB], S[IB], acc2[IB];
        int i0 = ibase + threadIdx.x * IB;
#pragma unroll
        for (int g = 0; g < IB; g++) {
            float2 e = emb[i0 + g];
            float x = e.x * SCALE, y = e.y * SCALE;
            M[g]  = pack2(-2.0f * x, -2.0f * x);
            N_[g] = pack2(-2.0f * y, -2.0f * y);
            float sq = fmaf(x, x, y * y);
            S[g]  = pack2(sq, sq);
            acc2[g] = pack2(0.0f, 0.0f);
        }

#pragma unroll 2
        for (int k = 0; k < TILE_J / 2; k += 2) {
            // j-quad: pairs k (j0,j1) and k+1 (j2,j3) -- 3 LDS.128 total
            ulonglong2 JX = *reinterpret_cast<const ulonglong2*>(&sxp[k]);
            ulonglong2 JY = *reinterpret_cast<const ulonglong2*>(&syp[k]);
            ulonglong2 JZ = *reinterpret_cast<const ulonglong2*>(&szp[k]);
#pragma unroll
            for (int g = 0; g < IB; g++) {
                // dA = (d_{i,j0}, d_{i,j1}), dB = (d_{i,j2}, d_{i,j3})
                u64 dA = fma2(M[g], JX.x, fma2(N_[g], JY.x, add2(JZ.x, S[g])));
                u64 dB = fma2(M[g], JX.y, fma2(N_[g], JY.y, add2(JZ.y, S[g])));
                // lane-wise 2-way combine: 1/dA + 1/dB = (dA+dB)*rcp(dA*dB)
                u64 pr = mul2(dA, dB);
                u64 sm = add2(dA, dB);
                float plo, phi;
                unpack2(pr, plo, phi);
                u64 r2 = pack2(frcp(plo), frcp(phi));
                acc2[g] = fma2(sm, r2, acc2[g]);
            }
        }

        double dsum = 0.0;
#pragma unroll
        for (int g = 0; g < IB; g++) {
            float lo, hi;
            unpack2(acc2[g], lo, hi);
            dsum += (double)lo + (double)hi;
        }
        if (bi != bj) dsum *= 2.0;  // symmetry doubling

#pragma unroll
        for (int o = 16; o > 0; o >>= 1)
            dsum += __shfl_down_sync(0xffffffffu, dsum, o);

        double* sred = reinterpret_cast<double*>(sxp);
        __syncthreads();
        if ((threadIdx.x & 31) == 0)
            sred[threadIdx.x >> 5] = dsum;
        __syncthreads();
        if (threadIdx.x == 0) {
            double v = 0.0;
#pragma unroll
            for (int w = 0; w < THREADS / 32; w++) v += sred[w];
            g_part[q] = v;
        }
    }

    // ================= phase 2: edge slice (1/144 of E) =================
    {
        int tid = q * THREADS + threadIdx.x;
        int stride = NPAIR_BLOCKS * THREADS;
        float s1 = 0.0f, sp = 0.0f, se = 0.0f;
        for (int e = tid; e < E; e += stride) {
            int h = heads[e], tl = tails[e];
            float2 A = emb[h];
            float2 B = emb[tl];
            float dx = A.x - B.x;
            float dy = A.y - B.y;
            float d2 = SCALE2 * fmaf(dx, dx, dy * dy);
            float pe = p[e];
            s1 = fmaf(pe, __logf(1.0f + d2), s1);  // p * log(1+d2)
            sp += pe;
            se = fmaf(pe, __logf(pe), se);          // p * log(p)
        }
        double d1 = (double)s1, d2s = (double)sp, d3 = (double)se;
#pragma unroll
        for (int o = 16; o > 0; o >>= 1) {
            d1  += __shfl_down_sync(0xffffffffu, d1, o);
            d2s += __shfl_down_sync(0xffffffffu, d2s, o);
            d3  += __shfl_down_sync(0xffffffffu, d3, o);
        }
        double* sh1 = reinterpret_cast<double*>(syp);
        double* sh2 = sh1 + (THREADS / 32);
        double* sh3 = sh2 + (THREADS / 32);
        __syncthreads();
        if ((threadIdx.x & 31) == 0) {
            int w = threadIdx.x >> 5;
            sh1[w] = d1; sh2[w] = d2s; sh3[w] = d3;
        }
        __syncthreads();
        if (threadIdx.x == 0) {
            double v1 = 0.0, v2 = 0.0, v3 = 0.0;
#pragma unroll
            for (int w = 0; w < THREADS / 32; w++) {
                v1 += sh1[w]; v2 += sh2[w]; v3 += sh3[w];
            }
            g_e1[q] = v1; g_e2[q] = v2; g_e3[q] = v3;
        }
    }

    // ================= phase 3: last block assembles the scalar =================
    int lastflag = 0;
    if (threadIdx.x == 0) {
        __threadfence();  // make this block's partials visible
        lastflag = (atomicAdd(&g_done, 1) == NPAIR_BLOCKS - 1) ? 1 : 0;
    }
    if (threadIdx.x < 32) {
        lastflag = __shfl_sync(0xffffffffu, lastflag, 0);
        if (lastflag) {
            __threadfence();  // acquire all other blocks' partials
            double z = 0.0, e1 = 0.0, e2 = 0.0, e3 = 0.0;
            for (int i = threadIdx.x; i < NPAIR_BLOCKS; i += 32) {
                z  += g_part[i];
                e1 += g_e1[i];
                e2 += g_e2[i];
                e3 += g_e3[i];
            }
#pragma unroll
            for (int o = 16; o > 0; o >>= 1) {
                z  += __shfl_down_sync(0xffffffffu, z, o);
                e1 += __shfl_down_sync(0xffffffffu, e1, o);
                e2 += __shfl_down_sync(0xffffffffu, e2, o);
                e3 += __shfl_down_sync(0xffffffffu, e3, o);
            }
            if (threadIdx.x == 0) {
                double Z = z - (double)n;  // remove diagonal (each term = 1)
                out[0] = (float)(e1 + log(Z) * e2 + e3);
                g_done = 0;  // self-reset for graph replay determinism
            }
        }
    }
}

// ---------------- launch ------------------------------------------------------
extern "C" void kernel_launch(void* const* d_in, const int* in_sizes, int n_in,
                              void* d_out, int out_size) {
    const float2* emb   = (const float2*)d_in[0];
    const float*  p     = (const float*)d_in[1];
    const int*    heads = (const int*)d_in[2];
    const int*    tails = (const int*)d_in[3];
    int n = in_sizes[0] / 2;
    int E = in_sizes[1];

    k_fused<<<NPAIR_BLOCKS, THREADS>>>(emb, p, heads, tails, E, n, (float*)d_out);
}